// round 16
// baseline (speedup 1.0000x reference)
#include <cuda_runtime.h>
#include <math.h>

#define NB 8
#define NP 19248
#define MDIM 32
#define TK 200
#define PHW 138
#define IMG 512
#define MIDW 64
#define GSAMP 16
#define GDIM 64
#define EPSV 1e-6f
#define CONF_TH 0.05f
#define NMS_TH 0.5f
#define MAXDET 100

#define NATT2 149  /* ceil(PHW*PHW/128) */
#define NVALS 19   /* ceil(NP/1024) */

// ------------------------------ scratch ------------------------------------
__device__ float g_conf_k[NB][TK];
__device__ int   g_validk[NB][TK];
__device__ float g_loc_k[NB][TK][4];
__device__ float g_mask_k[NB][TK][MDIM];
__device__ float g_Atab[NB][TK][MIDW];
__device__ float g_Btab[NB][TK][MIDW];
__device__ float g_iou[NB][TK][TK];
__device__ int   g_ioumaxI[NB][TK];
__device__ float g_final[NB][PHW * PHW];
__device__ unsigned long long g_acc_var;
__device__ unsigned long long g_acc_loss;

#define SCALE_V 262144.0          /* 2^18 */
#define SCALE_L 1099511627776.0   /* 2^40 */

__device__ __forceinline__ unsigned enc_float(float v) {
    unsigned u = __float_as_uint(v);
    return (u & 0x80000000u) ? ~u : (u | 0x80000000u);
}

// ------------------- top-k + MLP factor tables (fused) ---------------------
__global__ __launch_bounds__(1024) void topk_kernel(const float* __restrict__ conf,
                                                    const float* __restrict__ loc,
                                                    const float* __restrict__ mask,
                                                    const float* __restrict__ W1,
                                                    const float* __restrict__ b1) {
    int b = blockIdx.x;
    int tid = threadIdx.x;
    const float* cp = conf + (size_t)b * NP * 2;

    __shared__ unsigned hist[256];
    __shared__ int wtot[8];
    __shared__ unsigned s_prefix;
    __shared__ int s_remaining;
    __shared__ int s_cnt;
    __shared__ unsigned long long cand[1024];
    __shared__ unsigned long long s_sorted[TK];
    __shared__ int s_idx[TK];
    __shared__ float s_loc[TK * 4];

    if (b == 0 && tid == 0) { g_acc_var = 0ull; g_acc_loss = 0ull; }
    if (tid == 0) { s_prefix = 0u; s_remaining = TK; }

    // single global sweep: encode all values into registers (0 = OOB sentinel)
    unsigned enc[NVALS];
#pragma unroll
    for (int p = 0; p < NVALS; p++) {
        int i = tid + p * 1024;
        unsigned e = 0u;
        if (i < NP) {
            float c1 = cp[i * 2 + 1];
            float s = (c1 > CONF_TH) ? c1 : -1.0f;
            e = enc_float(s);
        }
        enc[p] = e;
    }
    __syncthreads();

    int lane = tid & 31;
    for (int pass = 0; pass < 3; pass++) {
        if (tid < 256) hist[tid] = 0u;
        __syncthreads();
        unsigned prefix = s_prefix;
        int shift_bin = 24 - 8 * pass;
#pragma unroll
        for (int p = 0; p < NVALS; p++) {
            unsigned e = enc[p];
            if (e != 0u) {
                unsigned hi = (pass == 0) ? 0u : (e >> (shift_bin + 8));
                if (hi == prefix) atomicAdd(&hist[(e >> shift_bin) & 0xFFu], 1u);
            }
        }
        __syncthreads();
        int rem = s_remaining;
        int h = 0, sfxv = 0;
        if (tid < 256) {
            h = (int)hist[tid];
            sfxv = h;
#pragma unroll
            for (int off = 1; off < 32; off <<= 1) {
                int n = __shfl_down_sync(0xFFFFFFFFu, sfxv, off);
                if (lane + off < 32) sfxv += n;
            }
            if (lane == 0) wtot[tid >> 5] = sfxv;
        }
        __syncthreads();
        if (tid < 256) {
            int add = 0;
            for (int wg = (tid >> 5) + 1; wg < 8; wg++) add += wtot[wg];
            int sfx = sfxv + add;
            int nxt = sfx - h;
            if (sfx >= rem && nxt < rem) {
                s_prefix = (s_prefix << 8) | (unsigned)tid;
                s_remaining = rem - nxt;
            }
        }
        __syncthreads();
    }

    if (tid == 0) s_cnt = 0;
    __syncthreads();
    unsigned thr24 = s_prefix;
#pragma unroll
    for (int p = 0; p < NVALS; p++) {
        unsigned e = enc[p];
        if (e != 0u && (e >> 8) >= thr24) {
            int i = tid + p * 1024;
            int pos = atomicAdd(&s_cnt, 1);
            if (pos < 1024)
                cand[pos] = ((unsigned long long)e << 32) |
                            (unsigned long long)(0xFFFFFFFFu - (unsigned)i);
        }
    }
    __syncthreads();
    int cnt = min(s_cnt, 1024);

    // rank-select
    if (tid < cnt) {
        unsigned long long key = cand[tid];
        int rank = 0;
        for (int i = 0; i < cnt; i++) rank += (cand[i] > key) ? 1 : 0;
        if (rank < TK) s_sorted[rank] = key;
    }
    __syncthreads();

    if (tid < TK) {
        unsigned long long key = s_sorted[tid];
        unsigned e = (unsigned)(key >> 32);
        int idx = (int)(0xFFFFFFFFu - (unsigned)(key & 0xFFFFFFFFull));
        unsigned u = (e & 0x80000000u) ? (e ^ 0x80000000u) : ~e;
        float v = __uint_as_float(u);
        int val = (v > CONF_TH) ? 1 : 0;
        g_validk[b][tid] = val;
        g_conf_k[b][tid] = val ? v : 0.0f;
        g_ioumaxI[b][tid] = 0;
        s_idx[tid] = idx;
    }
    __syncthreads();

    for (int t = tid; t < TK * 4; t += 1024) {
        int k = t >> 2, d = t & 3;
        float v = loc[((size_t)b * NP + s_idx[k]) * 4 + d];
        g_loc_k[b][k][d] = v;
        s_loc[t] = v;
    }
    for (int t = tid; t < TK * MDIM; t += 1024) {
        int k = t >> 5, d = t & 31;
        g_mask_k[b][k][d] = mask[((size_t)b * NP + s_idx[k]) * MDIM + d];
    }
    __syncthreads();

    for (int t = tid; t < TK * MIDW; t += 1024) {
        int k = t / MIDW, h = t % MIDW;
        float l0 = s_loc[k * 4 + 0], l1 = s_loc[k * 4 + 1];
        float l2 = s_loc[k * 4 + 2], l3 = s_loc[k * 4 + 3];
        float a = fmaf(l3, W1[3 * MIDW + h],
                  fmaf(l2, W1[2 * MIDW + h],
                  fmaf(l1, W1[1 * MIDW + h], l0 * W1[h])));
        float bb = fmaf(l3, W1[7 * MIDW + h],
                   fmaf(l2, W1[6 * MIDW + h],
                   fmaf(l1, W1[5 * MIDW + h], l0 * W1[4 * MIDW + h]))) + b1[h];
        g_Atab[b][k][h] = a;
        g_Btab[b][k][h] = bb;
    }
}

// -------------------------- 200x200 IoU MLP + column max -------------------
__global__ void mlp_kernel(const float* __restrict__ W2, const float* __restrict__ b2) {
    int b = blockIdx.z;
    int jb = blockIdx.x * 16, ib = blockIdx.y * 16;
    __shared__ float As[16][MIDW + 1];
    __shared__ float Bs[16][MIDW + 1];
    __shared__ float w2s[MIDW];
    __shared__ float s_b2;
    __shared__ int s_vi[16], s_vj[16];
    int tid = threadIdx.x;
    for (int t = tid; t < 16 * MIDW; t += 256) {
        int r = t / MIDW, h = t % MIDW;
        As[r][h] = (jb + r < TK) ? g_Atab[b][jb + r][h] : 0.0f;
        Bs[r][h] = (ib + r < TK) ? g_Btab[b][ib + r][h] : 0.0f;
    }
    if (tid < MIDW) w2s[tid] = W2[tid];
    if (tid == 0) s_b2 = b2[0];
    if (tid < 16) {
        s_vj[tid] = (jb + tid < TK) ? g_validk[b][jb + tid] : 0;
        s_vi[tid] = (ib + tid < TK) ? g_validk[b][ib + tid] : 0;
    }
    __syncthreads();
    int tj = tid & 15, ti = tid >> 4;
    int i = ib + ti, j = jb + tj;
    if (i < TK && j < TK) {
        float acc = s_b2;
#pragma unroll
        for (int h = 0; h < MIDW; h++) {
            float s = As[tj][h] + Bs[ti][h];
            acc = fmaf(fmaxf(s, 0.0f), w2s[h], acc);
        }
        float iou = __fdividef(1.0f, 1.0f + __expf(-acc));
        g_iou[b][i][j] = iou;
        if (i < j && s_vi[ti] && s_vj[tj])
            atomicMax(&g_ioumaxI[b][j], __float_as_int(iou));
    }
}

// ---- attention + loss (NMS scan redone locally, gaussians inline) ---------
__global__ __launch_bounds__(256) void attn_loss_kernel(const float* __restrict__ proto) {
    int b = blockIdx.y;
    int tid = threadIdx.x;

    // ---- local NMS scan (deterministic, same result in every block) ----
    __shared__ int s_perm[TK];
    __shared__ int wsum[8];
    __shared__ int s_nk;
    {
        int keep = 0;
        if (tid < TK) {
            int valid = g_validk[b][tid];
            float m = __int_as_float(g_ioumaxI[b][tid]);
            keep = (valid && m <= NMS_TH) ? 1 : 0;
        }
        int lane = tid & 31, wid = tid >> 5;
        int v = keep;
#pragma unroll
        for (int o = 1; o < 32; o <<= 1) {
            int n = __shfl_up_sync(0xFFFFFFFFu, v, o);
            if (lane >= o) v += n;
        }
        if (lane == 31) wsum[wid] = v;
        __syncthreads();
        if (tid < 8) {
            int w = wsum[tid];
#pragma unroll
            for (int o = 1; o < 8; o <<= 1) {
                int n = __shfl_up_sync(0xFFu, w, o);
                if ((int)tid >= o) w += n;
            }
            wsum[tid] = w;
        }
        __syncthreads();
        int incl = v + (wid ? wsum[wid - 1] : 0);
        int total = wsum[7];
        int nk = min(total, MAXDET);
        int keep2 = keep && (incl <= MAXDET);
        int incl2 = min(incl, MAXDET);
        if (tid == 0) s_nk = nk;
        if (tid < TK) {
            int pos = keep2 ? (incl2 - 1) : (nk + tid - incl2);
            s_perm[pos] = tid;
        }
        __syncthreads();
    }
    int nk = s_nk;

    if (blockIdx.x >= NATT2) {
        // -------------------- loss part --------------------
        int p = blockIdx.x - NATT2;
        int g = min(GSAMP, nk);
        if (p >= g) return;
        __shared__ __align__(16) float sy[GSAMP][GDIM];
        __shared__ __align__(16) float sx[GSAMP][GDIM];
        for (int t = tid; t < g * GDIM; t += 256) {
            int k = t >> 6, i = t & 63;
            int pk = s_perm[k];
            float cx = g_loc_k[b][pk][0], cy = g_loc_k[b][pk][1];
            float bw = g_loc_k[b][pk][2], bh = g_loc_k[b][pk][3];
            float s = (i + 0.5f) / (float)GDIM;
            float ty = (s - cy) / (bh * 0.5f + EPSV);
            float tx = (s - cx) / (bw * 0.5f + EPSV);
            sy[k][i] = __expf(-0.5f * ty * ty);
            sx[k][i] = __expf(-0.5f * tx * tx);
        }
        __syncthreads();
        int warp = tid >> 5, lane = tid & 31;
        const float* gyp = sy[p];
        const float* gxp = sx[p];
        int ip = s_perm[p];
        for (int q = warp; q < g; q += 8) {
            const float* gyq = sy[q];
            const float* gxq = sx[q];
            float inter = 0.0f, uni = 0.0f;
            for (int px = lane; px < GDIM * GDIM; px += 32) {
                int y = px >> 6, x = px & 63;
                float a = gyp[y] * gxp[x];
                float c = gyq[y] * gxq[x];
                inter += fminf(a, c);
                uni += fmaxf(a, c);
            }
#pragma unroll
            for (int o = 16; o > 0; o >>= 1) {
                inter += __shfl_down_sync(0xFFFFFFFFu, inter, o);
                uni   += __shfl_down_sync(0xFFFFFFFFu, uni, o);
            }
            if (lane == 0) {
                float giou = inter / (uni + EPSV);
                float pred = g_iou[b][ip][s_perm[q]];
                float d = pred - giou;
                atomicAdd(&g_acc_loss,
                          (unsigned long long)((double)(d * d) * SCALE_L + 0.5));
            }
        }
        return;
    }

    // -------------------- attention part --------------------
    __shared__ __align__(16) float s_mask[MAXDET * MDIM];
    __shared__ float s_cx[MAXDET], s_cy[MAXDET];
    __shared__ float s_iw[MAXDET], s_ih[MAXDET];
    __shared__ float s_cf[MAXDET];
    if (tid < nk) {
        int pk = s_perm[tid];
        s_cx[tid] = g_loc_k[b][pk][0];
        s_cy[tid] = g_loc_k[b][pk][1];
        s_iw[tid] = 1.0f / (g_loc_k[b][pk][2] * 0.5f + EPSV);
        s_ih[tid] = 1.0f / (g_loc_k[b][pk][3] * 0.5f + EPSV);
        s_cf[tid] = g_conf_k[b][pk];
    }
    __syncthreads();
    for (int t = tid; t < nk * MDIM; t += 256)
        s_mask[t] = g_mask_k[b][s_perm[t >> 5]][t & 31];
    __syncthreads();

    int pix = blockIdx.x * 128 + (tid >> 1);
    int half = tid & 1;
    bool live = pix < PHW * PHW;
    int pixc = live ? pix : 0;
    int y = pixc / PHW, x = pixc % PHW;
    float ys = (y + 0.5f) / (float)PHW;
    float xs = (x + 0.5f) / (float)PHW;
    const float4* pp = reinterpret_cast<const float4*>(
        proto + ((size_t)b * (PHW * PHW) + pixc) * MDIM + half * 16);
    float4 pr[4];
#pragma unroll
    for (int i = 0; i < 4; i++) pr[i] = pp[i];

    float s1 = 0.0f, s2 = 0.0f;
    for (int k = 0; k < nk; k++) {
        const float4* mk = reinterpret_cast<const float4*>(&s_mask[k * MDIM + half * 16]);
        float pd = 0.0f;
#pragma unroll
        for (int i = 0; i < 4; i++) {
            float4 m = mk[i];
            pd = fmaf(pr[i].x, m.x, pd);
            pd = fmaf(pr[i].y, m.y, pd);
            pd = fmaf(pr[i].z, m.z, pd);
            pd = fmaf(pr[i].w, m.w, pd);
        }
        float dot = pd + __shfl_xor_sync(0xFFFFFFFFu, pd, 1);
        float sg = __fdividef(1.0f, 1.0f + __expf(-dot));
        float ty = (ys - s_cy[k]) * s_ih[k];
        float tx = (xs - s_cx[k]) * s_iw[k];
        float g = __expf(-0.5f * fmaf(ty, ty, tx * tx));
        float mv = sg * g * s_cf[k];
        s1 += mv;
        s2 = fmaf(mv, mv, s2);
    }
    if (live && half == 0)
        g_final[b][pix] = 1.0f - s2 / (s1 + EPSV);
}

// --------- fused resize + variance, float4 (4 pixels/thread) ---------------
// Sum_b r_b * Sum_c (o_cb - wm_c)^2  =  S2 + W*(tot - 2)  per pixel.
__global__ __launch_bounds__(256) void fusedvar_kernel(const float* __restrict__ original) {
    int tid = threadIdx.x;
    int p4 = (blockIdx.x * 256 + tid) * 4;   // 4 consecutive pixels, same row
    int y = p4 >> 9;
    int xbase = p4 & 511;

    const float S = (float)PHW / (float)IMG;
    float syc = (y + 0.5f) * S - 0.5f;
    float fy = floorf(syc);
    float wy = syc - fy;
    int y0 = max((int)fy, 0), y1 = min((int)fy + 1, PHW - 1);

    int x0[4], x1[4];
    float wx[4];
#pragma unroll
    for (int j = 0; j < 4; j++) {
        float sxc = (xbase + j + 0.5f) * S - 0.5f;
        float fx = floorf(sxc);
        wx[j] = sxc - fx;
        x0[j] = max((int)fx, 0);
        x1[j] = min((int)fx + 1, PHW - 1);
    }

    float tot[4] = {0, 0, 0, 0};
    float wm0[4] = {0, 0, 0, 0}, wm1[4] = {0, 0, 0, 0}, wm2[4] = {0, 0, 0, 0};
    float S2[4] = {0, 0, 0, 0};

#pragma unroll
    for (int b = 0; b < NB; b++) {
        const float* rt = &g_final[b][y0 * PHW];
        const float* rb = &g_final[b][y1 * PHW];
        size_t base = ((size_t)b * 3) * (IMG * IMG) + p4;
        float4 o0 = *reinterpret_cast<const float4*>(original + base);
        float4 o1 = *reinterpret_cast<const float4*>(original + base + IMG * IMG);
        float4 o2 = *reinterpret_cast<const float4*>(original + base + 2 * IMG * IMG);
        float a0[4] = {o0.x, o0.y, o0.z, o0.w};
        float a1[4] = {o1.x, o1.y, o1.z, o1.w};
        float a2[4] = {o2.x, o2.y, o2.z, o2.w};
#pragma unroll
        for (int j = 0; j < 4; j++) {
            float t0 = rt[x0[j]], t1 = rt[x1[j]];
            float b0 = rb[x0[j]], b1v = rb[x1[j]];
            float top = t0 + (t1 - t0) * wx[j];
            float bot = b0 + (b1v - b0) * wx[j];
            float r = top + (bot - top) * wy;
            tot[j] += r;
            wm0[j] = fmaf(a0[j], r, wm0[j]);
            wm1[j] = fmaf(a1[j], r, wm1[j]);
            wm2[j] = fmaf(a2[j], r, wm2[j]);
            S2[j] = fmaf(r, fmaf(a0[j], a0[j], fmaf(a1[j], a1[j], a2[j] * a2[j])), S2[j]);
        }
    }

    float acc = 0.0f;
#pragma unroll
    for (int j = 0; j < 4; j++) {
        float W = fmaf(wm0[j], wm0[j], fmaf(wm1[j], wm1[j], wm2[j] * wm2[j]));
        acc += (S2[j] + W * (tot[j] - 2.0f)) / (tot[j] + EPSV);
    }

    for (int o = 16; o > 0; o >>= 1) acc += __shfl_down_sync(0xFFFFFFFFu, acc, o);
    __shared__ float rs[8];
    int w = tid >> 5;
    if ((tid & 31) == 0) rs[w] = acc;
    __syncthreads();
    if (tid == 0) {
        float s = 0.0f;
#pragma unroll
        for (int i = 0; i < 8; i++) s += rs[i];
        atomicAdd(&g_acc_var, (unsigned long long)((double)s * SCALE_V + 0.5));
    }
}

// ------------------------------ finalize -----------------------------------
__global__ void finalize_kernel(float* __restrict__ out) {
    out[0] = (float)((double)g_acc_var / SCALE_V);
    out[1] = (float)((double)g_acc_loss / SCALE_L);
}

// ------------------------------ launcher -----------------------------------
extern "C" void kernel_launch(void* const* d_in, const int* in_sizes, int n_in,
                              void* d_out, int out_size) {
    const float* original = (const float*)d_in[0];
    const float* loc      = (const float*)d_in[1];
    const float* conf     = (const float*)d_in[2];
    const float* mask     = (const float*)d_in[3];
    const float* proto    = (const float*)d_in[4];
    const float* W1       = (const float*)d_in[5];
    const float* b1       = (const float*)d_in[6];
    const float* W2       = (const float*)d_in[7];
    const float* b2       = (const float*)d_in[8];
    float* out = (float*)d_out;

    topk_kernel<<<NB, 1024>>>(conf, loc, mask, W1, b1);
    mlp_kernel<<<dim3((TK + 15) / 16, (TK + 15) / 16, NB), 256>>>(W2, b2);
    attn_loss_kernel<<<dim3(NATT2 + GSAMP, NB), 256>>>(proto);
    fusedvar_kernel<<<(IMG * IMG) / 1024, 256>>>(original);
    finalize_kernel<<<1, 1>>>(out);
}

// round 17
// speedup vs baseline: 1.0416x; 1.0416x over previous
#include <cuda_runtime.h>
#include <math.h>

#define NB 8
#define NP 19248
#define MDIM 32
#define TK 200
#define PHW 138
#define IMG 512
#define MIDW 64
#define GSAMP 16
#define GDIM 64
#define EPSV 1e-6f
#define CONF_TH 0.05f
#define NMS_TH 0.5f
#define MAXDET 100

#define NATT2 149  /* ceil(PHW*PHW/128) */
#define NVALS 19   /* ceil(NP/1024) */
#define FVGRID 1024 /* fusedvar grid: IMG*IMG/256 */

// ------------------------------ scratch ------------------------------------
__device__ float g_conf_k[NB][TK];
__device__ int   g_validk[NB][TK];
__device__ float g_loc_k[NB][TK][4];
__device__ float g_mask_k[NB][TK][MDIM];
__device__ float g_Atab[NB][TK][MIDW];
__device__ float g_Btab[NB][TK][MIDW];
__device__ float g_iou[NB][TK][TK];
__device__ int   g_ioumaxI[NB][TK];
__device__ float g_final[NB][PHW * PHW];
__device__ unsigned long long g_acc_var;
__device__ unsigned long long g_acc_loss;
__device__ unsigned int g_done;

#define SCALE_V 262144.0          /* 2^18 */
#define SCALE_L 1099511627776.0   /* 2^40 */

__device__ __forceinline__ unsigned enc_float(float v) {
    unsigned u = __float_as_uint(v);
    return (u & 0x80000000u) ? ~u : (u | 0x80000000u);
}

// ------------------- top-k + MLP factor tables (fused) ---------------------
__global__ __launch_bounds__(1024) void topk_kernel(const float* __restrict__ conf,
                                                    const float* __restrict__ loc,
                                                    const float* __restrict__ mask,
                                                    const float* __restrict__ W1,
                                                    const float* __restrict__ b1) {
    int b = blockIdx.x;
    int tid = threadIdx.x;
    const float* cp = conf + (size_t)b * NP * 2;

    __shared__ unsigned hist[256];
    __shared__ int wtot[8];
    __shared__ unsigned s_prefix;
    __shared__ int s_remaining;
    __shared__ int s_cnt;
    __shared__ unsigned long long cand[1024];
    __shared__ unsigned long long s_sorted[TK];
    __shared__ int s_idx[TK];
    __shared__ float s_loc[TK * 4];

    if (b == 0 && tid == 0) { g_acc_var = 0ull; g_acc_loss = 0ull; g_done = 0u; }
    if (tid == 0) { s_prefix = 0u; s_remaining = TK; }

    // single global sweep: encode all values into registers (0 = OOB sentinel)
    unsigned enc[NVALS];
#pragma unroll
    for (int p = 0; p < NVALS; p++) {
        int i = tid + p * 1024;
        unsigned e = 0u;
        if (i < NP) {
            float c1 = cp[i * 2 + 1];
            float s = (c1 > CONF_TH) ? c1 : -1.0f;
            e = enc_float(s);
        }
        enc[p] = e;
    }
    __syncthreads();

    int lane = tid & 31;
    for (int pass = 0; pass < 3; pass++) {
        if (tid < 256) hist[tid] = 0u;
        __syncthreads();
        unsigned prefix = s_prefix;
        int shift_bin = 24 - 8 * pass;
#pragma unroll
        for (int p = 0; p < NVALS; p++) {
            unsigned e = enc[p];
            if (e != 0u) {
                unsigned hi = (pass == 0) ? 0u : (e >> (shift_bin + 8));
                if (hi == prefix) atomicAdd(&hist[(e >> shift_bin) & 0xFFu], 1u);
            }
        }
        __syncthreads();
        int rem = s_remaining;
        int h = 0, sfxv = 0;
        if (tid < 256) {
            h = (int)hist[tid];
            sfxv = h;
#pragma unroll
            for (int off = 1; off < 32; off <<= 1) {
                int n = __shfl_down_sync(0xFFFFFFFFu, sfxv, off);
                if (lane + off < 32) sfxv += n;
            }
            if (lane == 0) wtot[tid >> 5] = sfxv;
        }
        __syncthreads();
        if (tid < 256) {
            int add = 0;
            for (int wg = (tid >> 5) + 1; wg < 8; wg++) add += wtot[wg];
            int sfx = sfxv + add;
            int nxt = sfx - h;
            if (sfx >= rem && nxt < rem) {
                s_prefix = (s_prefix << 8) | (unsigned)tid;
                s_remaining = rem - nxt;
            }
        }
        __syncthreads();
    }

    if (tid == 0) s_cnt = 0;
    __syncthreads();
    unsigned thr24 = s_prefix;
#pragma unroll
    for (int p = 0; p < NVALS; p++) {
        unsigned e = enc[p];
        if (e != 0u && (e >> 8) >= thr24) {
            int i = tid + p * 1024;
            int pos = atomicAdd(&s_cnt, 1);
            if (pos < 1024)
                cand[pos] = ((unsigned long long)e << 32) |
                            (unsigned long long)(0xFFFFFFFFu - (unsigned)i);
        }
    }
    __syncthreads();
    int cnt = min(s_cnt, 1024);

    // rank-select
    if (tid < cnt) {
        unsigned long long key = cand[tid];
        int rank = 0;
        for (int i = 0; i < cnt; i++) rank += (cand[i] > key) ? 1 : 0;
        if (rank < TK) s_sorted[rank] = key;
    }
    __syncthreads();

    if (tid < TK) {
        unsigned long long key = s_sorted[tid];
        unsigned e = (unsigned)(key >> 32);
        int idx = (int)(0xFFFFFFFFu - (unsigned)(key & 0xFFFFFFFFull));
        unsigned u = (e & 0x80000000u) ? (e ^ 0x80000000u) : ~e;
        float v = __uint_as_float(u);
        int val = (v > CONF_TH) ? 1 : 0;
        g_validk[b][tid] = val;
        g_conf_k[b][tid] = val ? v : 0.0f;
        g_ioumaxI[b][tid] = 0;
        s_idx[tid] = idx;
    }
    __syncthreads();

    for (int t = tid; t < TK * 4; t += 1024) {
        int k = t >> 2, d = t & 3;
        float v = loc[((size_t)b * NP + s_idx[k]) * 4 + d];
        g_loc_k[b][k][d] = v;
        s_loc[t] = v;
    }
    for (int t = tid; t < TK * MDIM; t += 1024) {
        int k = t >> 5, d = t & 31;
        g_mask_k[b][k][d] = mask[((size_t)b * NP + s_idx[k]) * MDIM + d];
    }
    __syncthreads();

    for (int t = tid; t < TK * MIDW; t += 1024) {
        int k = t / MIDW, h = t % MIDW;
        float l0 = s_loc[k * 4 + 0], l1 = s_loc[k * 4 + 1];
        float l2 = s_loc[k * 4 + 2], l3 = s_loc[k * 4 + 3];
        float a = fmaf(l3, W1[3 * MIDW + h],
                  fmaf(l2, W1[2 * MIDW + h],
                  fmaf(l1, W1[1 * MIDW + h], l0 * W1[h])));
        float bb = fmaf(l3, W1[7 * MIDW + h],
                   fmaf(l2, W1[6 * MIDW + h],
                   fmaf(l1, W1[5 * MIDW + h], l0 * W1[4 * MIDW + h]))) + b1[h];
        g_Atab[b][k][h] = a;
        g_Btab[b][k][h] = bb;
    }
}

// -------------- 200x200 IoU MLP (32x32 tiles, 2x2/thread) + col max --------
__global__ __launch_bounds__(256) void mlp_kernel(const float* __restrict__ W2,
                                                  const float* __restrict__ b2) {
    int b = blockIdx.z;
    int jb = blockIdx.x * 32, ib = blockIdx.y * 32;
    __shared__ float As[32][MIDW + 1];
    __shared__ float Bs[32][MIDW + 1];
    __shared__ float w2s[MIDW];
    __shared__ float s_b2;
    __shared__ int s_vi[32], s_vj[32];
    int tid = threadIdx.x;
    for (int t = tid; t < 32 * MIDW; t += 256) {
        int r = t / MIDW, h = t % MIDW;
        As[r][h] = (jb + r < TK) ? g_Atab[b][jb + r][h] : 0.0f;
        Bs[r][h] = (ib + r < TK) ? g_Btab[b][ib + r][h] : 0.0f;
    }
    if (tid < MIDW) w2s[tid] = W2[tid];
    if (tid == 0) s_b2 = b2[0];
    if (tid < 32) {
        s_vj[tid] = (jb + tid < TK) ? g_validk[b][jb + tid] : 0;
        s_vi[tid] = (ib + tid < TK) ? g_validk[b][ib + tid] : 0;
    }
    __syncthreads();
    int tj2 = (tid & 15) * 2, ti2 = (tid >> 4) * 2;
    float bse = s_b2;
    float a00 = bse, a01 = bse, a10 = bse, a11 = bse;
#pragma unroll
    for (int h = 0; h < MIDW; h++) {
        float w = w2s[h];
        float aj0 = As[tj2][h], aj1 = As[tj2 + 1][h];
        float bi0 = Bs[ti2][h], bi1 = Bs[ti2 + 1][h];
        a00 = fmaf(fmaxf(aj0 + bi0, 0.0f), w, a00);
        a01 = fmaf(fmaxf(aj1 + bi0, 0.0f), w, a01);
        a10 = fmaf(fmaxf(aj0 + bi1, 0.0f), w, a10);
        a11 = fmaf(fmaxf(aj1 + bi1, 0.0f), w, a11);
    }
#pragma unroll
    for (int di = 0; di < 2; di++) {
#pragma unroll
        for (int dj = 0; dj < 2; dj++) {
            int i = ib + ti2 + di, j = jb + tj2 + dj;
            if (i < TK && j < TK) {
                float acc = (di == 0) ? ((dj == 0) ? a00 : a01)
                                      : ((dj == 0) ? a10 : a11);
                float iou = __fdividef(1.0f, 1.0f + __expf(-acc));
                g_iou[b][i][j] = iou;
                if (i < j && s_vi[ti2 + di] && s_vj[tj2 + dj])
                    atomicMax(&g_ioumaxI[b][j], __float_as_int(iou));
            }
        }
    }
}

// ---- attention + loss (NMS scan redone locally, gaussians inline) ---------
__global__ __launch_bounds__(256) void attn_loss_kernel(const float* __restrict__ proto) {
    int b = blockIdx.y;
    int tid = threadIdx.x;

    // ---- local NMS scan (deterministic, same result in every block) ----
    __shared__ int s_perm[TK];
    __shared__ int wsum[8];
    __shared__ int s_nk;
    {
        int keep = 0;
        if (tid < TK) {
            int valid = g_validk[b][tid];
            float m = __int_as_float(g_ioumaxI[b][tid]);
            keep = (valid && m <= NMS_TH) ? 1 : 0;
        }
        int lane = tid & 31, wid = tid >> 5;
        int v = keep;
#pragma unroll
        for (int o = 1; o < 32; o <<= 1) {
            int n = __shfl_up_sync(0xFFFFFFFFu, v, o);
            if (lane >= o) v += n;
        }
        if (lane == 31) wsum[wid] = v;
        __syncthreads();
        if (tid < 8) {
            int w = wsum[tid];
#pragma unroll
            for (int o = 1; o < 8; o <<= 1) {
                int n = __shfl_up_sync(0xFFu, w, o);
                if ((int)tid >= o) w += n;
            }
            wsum[tid] = w;
        }
        __syncthreads();
        int incl = v + (wid ? wsum[wid - 1] : 0);
        int total = wsum[7];
        int nk = min(total, MAXDET);
        int keep2 = keep && (incl <= MAXDET);
        int incl2 = min(incl, MAXDET);
        if (tid == 0) s_nk = nk;
        if (tid < TK) {
            int pos = keep2 ? (incl2 - 1) : (nk + tid - incl2);
            s_perm[pos] = tid;
        }
        __syncthreads();
    }
    int nk = s_nk;

    if (blockIdx.x >= NATT2) {
        // -------------------- loss part --------------------
        int p = blockIdx.x - NATT2;
        int g = min(GSAMP, nk);
        if (p >= g) return;
        __shared__ __align__(16) float sy[GSAMP][GDIM];
        __shared__ __align__(16) float sx[GSAMP][GDIM];
        for (int t = tid; t < g * GDIM; t += 256) {
            int k = t >> 6, i = t & 63;
            int pk = s_perm[k];
            float cx = g_loc_k[b][pk][0], cy = g_loc_k[b][pk][1];
            float bw = g_loc_k[b][pk][2], bh = g_loc_k[b][pk][3];
            float s = (i + 0.5f) / (float)GDIM;
            float ty = (s - cy) / (bh * 0.5f + EPSV);
            float tx = (s - cx) / (bw * 0.5f + EPSV);
            sy[k][i] = __expf(-0.5f * ty * ty);
            sx[k][i] = __expf(-0.5f * tx * tx);
        }
        __syncthreads();
        int warp = tid >> 5, lane = tid & 31;
        const float* gyp = sy[p];
        const float* gxp = sx[p];
        int ip = s_perm[p];
        for (int q = warp; q < g; q += 8) {
            const float* gyq = sy[q];
            const float* gxq = sx[q];
            float inter = 0.0f, uni = 0.0f;
            for (int px = lane; px < GDIM * GDIM; px += 32) {
                int y = px >> 6, x = px & 63;
                float a = gyp[y] * gxp[x];
                float c = gyq[y] * gxq[x];
                inter += fminf(a, c);
                uni += fmaxf(a, c);
            }
#pragma unroll
            for (int o = 16; o > 0; o >>= 1) {
                inter += __shfl_down_sync(0xFFFFFFFFu, inter, o);
                uni   += __shfl_down_sync(0xFFFFFFFFu, uni, o);
            }
            if (lane == 0) {
                float giou = inter / (uni + EPSV);
                float pred = g_iou[b][ip][s_perm[q]];
                float d = pred - giou;
                atomicAdd(&g_acc_loss,
                          (unsigned long long)((double)(d * d) * SCALE_L + 0.5));
            }
        }
        return;
    }

    // -------------------- attention part --------------------
    __shared__ __align__(16) float s_mask[MAXDET * MDIM];
    __shared__ float s_cx[MAXDET], s_cy[MAXDET];
    __shared__ float s_iw[MAXDET], s_ih[MAXDET];
    __shared__ float s_cf[MAXDET];
    if (tid < nk) {
        int pk = s_perm[tid];
        s_cx[tid] = g_loc_k[b][pk][0];
        s_cy[tid] = g_loc_k[b][pk][1];
        s_iw[tid] = 1.0f / (g_loc_k[b][pk][2] * 0.5f + EPSV);
        s_ih[tid] = 1.0f / (g_loc_k[b][pk][3] * 0.5f + EPSV);
        s_cf[tid] = g_conf_k[b][pk];
    }
    __syncthreads();
    for (int t = tid; t < nk * MDIM; t += 256)
        s_mask[t] = g_mask_k[b][s_perm[t >> 5]][t & 31];
    __syncthreads();

    int pix = blockIdx.x * 128 + (tid >> 1);
    int half = tid & 1;
    bool live = pix < PHW * PHW;
    int pixc = live ? pix : 0;
    int y = pixc / PHW, x = pixc % PHW;
    float ys = (y + 0.5f) / (float)PHW;
    float xs = (x + 0.5f) / (float)PHW;
    const float4* pp = reinterpret_cast<const float4*>(
        proto + ((size_t)b * (PHW * PHW) + pixc) * MDIM + half * 16);
    float4 pr[4];
#pragma unroll
    for (int i = 0; i < 4; i++) pr[i] = pp[i];

    float s1 = 0.0f, s2 = 0.0f;
    for (int k = 0; k < nk; k++) {
        const float4* mk = reinterpret_cast<const float4*>(&s_mask[k * MDIM + half * 16]);
        float pd = 0.0f;
#pragma unroll
        for (int i = 0; i < 4; i++) {
            float4 m = mk[i];
            pd = fmaf(pr[i].x, m.x, pd);
            pd = fmaf(pr[i].y, m.y, pd);
            pd = fmaf(pr[i].z, m.z, pd);
            pd = fmaf(pr[i].w, m.w, pd);
        }
        float dot = pd + __shfl_xor_sync(0xFFFFFFFFu, pd, 1);
        float sg = __fdividef(1.0f, 1.0f + __expf(-dot));
        float ty = (ys - s_cy[k]) * s_ih[k];
        float tx = (xs - s_cx[k]) * s_iw[k];
        float g = __expf(-0.5f * fmaf(ty, ty, tx * tx));
        float mv = sg * g * s_cf[k];
        s1 += mv;
        s2 = fmaf(mv, mv, s2);
    }
    if (live && half == 0)
        g_final[b][pix] = 1.0f - s2 / (s1 + EPSV);
}

// --------- fused resize + variance (one-pass algebraic) + finalize ---------
// Sum_b r_b * Sum_c (o_cb - wm_c)^2  =  S2 + W*(tot - 2) per pixel.
__device__ __forceinline__ void resize_coords(int y, int x, int& y0, int& y1,
                                              int& x0, int& x1, float& wy, float& wx) {
    const float S = (float)PHW / (float)IMG;
    float sy = (y + 0.5f) * S - 0.5f;
    float sx = (x + 0.5f) * S - 0.5f;
    float fy = floorf(sy), fx = floorf(sx);
    wy = sy - fy;
    wx = sx - fx;
    y0 = max((int)fy, 0); y1 = min((int)fy + 1, PHW - 1);
    x0 = max((int)fx, 0); x1 = min((int)fx + 1, PHW - 1);
}

__device__ __forceinline__ float bilerp(const float* fb, int y0, int y1, int x0,
                                        int x1, float wy, float wx) {
    float a = fb[y0 * PHW + x0], b = fb[y0 * PHW + x1];
    float c = fb[y1 * PHW + x0], d = fb[y1 * PHW + x1];
    float top = a + (b - a) * wx;
    float bot = c + (d - c) * wx;
    return top + (bot - top) * wy;
}

__global__ __launch_bounds__(256) void fusedvar_kernel(const float* __restrict__ original,
                                                       float* __restrict__ out) {
    int p = blockIdx.x * blockDim.x + threadIdx.x;
    int tid = threadIdx.x;
    float acc = 0.0f;
    if (p < IMG * IMG) {
        int y = p >> 9, x = p & 511;
        int y0, y1, x0, x1; float wy, wx;
        resize_coords(y, x, y0, y1, x0, x1, wy, wx);
        float tot = 0.0f, wm0 = 0.0f, wm1 = 0.0f, wm2 = 0.0f, S2 = 0.0f;
#pragma unroll
        for (int b = 0; b < NB; b++) {
            float r = bilerp(g_final[b], y0, y1, x0, x1, wy, wx);
            tot += r;
            size_t base = ((size_t)b * 3) * (IMG * IMG) + p;
            float o0 = original[base];
            float o1 = original[base + IMG * IMG];
            float o2 = original[base + 2 * IMG * IMG];
            wm0 = fmaf(o0, r, wm0);
            wm1 = fmaf(o1, r, wm1);
            wm2 = fmaf(o2, r, wm2);
            S2 = fmaf(r, fmaf(o0, o0, fmaf(o1, o1, o2 * o2)), S2);
        }
        float W = fmaf(wm0, wm0, fmaf(wm1, wm1, wm2 * wm2));
        acc = (S2 + W * (tot - 2.0f)) / (tot + EPSV);
    }
    for (int o = 16; o > 0; o >>= 1) acc += __shfl_down_sync(0xFFFFFFFFu, acc, o);
    __shared__ float rs[8];
    int w = tid >> 5;
    if ((tid & 31) == 0) rs[w] = acc;
    __syncthreads();
    if (tid == 0) {
        float s = 0.0f;
#pragma unroll
        for (int i = 0; i < 8; i++) s += rs[i];
        atomicAdd(&g_acc_var, (unsigned long long)((double)s * SCALE_V + 0.5));
        __threadfence();
        unsigned int done = atomicAdd(&g_done, 1u);
        if (done == FVGRID - 1) {
            unsigned long long av = atomicAdd(&g_acc_var, 0ull);
            unsigned long long al = atomicAdd(&g_acc_loss, 0ull);
            out[0] = (float)((double)av / SCALE_V);
            out[1] = (float)((double)al / SCALE_L);
        }
    }
}

// ------------------------------ launcher -----------------------------------
extern "C" void kernel_launch(void* const* d_in, const int* in_sizes, int n_in,
                              void* d_out, int out_size) {
    const float* original = (const float*)d_in[0];
    const float* loc      = (const float*)d_in[1];
    const float* conf     = (const float*)d_in[2];
    const float* mask     = (const float*)d_in[3];
    const float* proto    = (const float*)d_in[4];
    const float* W1       = (const float*)d_in[5];
    const float* b1       = (const float*)d_in[6];
    const float* W2       = (const float*)d_in[7];
    const float* b2       = (const float*)d_in[8];
    float* out = (float*)d_out;

    topk_kernel<<<NB, 1024>>>(conf, loc, mask, W1, b1);
    mlp_kernel<<<dim3((TK + 31) / 32, (TK + 31) / 32, NB), 256>>>(W2, b2);
    attn_loss_kernel<<<dim3(NATT2 + GSAMP, NB), 256>>>(proto);
    fusedvar_kernel<<<FVGRID, 256>>>(original, out);
}